// round 17
// baseline (speedup 1.0000x reference)
#include <cuda_runtime.h>
#include <cuda_bf16.h>

// Problem constants
#define BB 2
#define NN 8192
#define CC 64
#define DD 3
#define MM 2048   // NPOINT
#define SS 32     // NSAMPLE

// Output layout (concatenated tuple, row-major each)
#define OFF_GXYZ 0L
#define OFF_GFTS 393216L
#define OFF_NXYZ (393216L + 50331648L)
#define OFF_NFTS (393216L + 50331648L + 12288L)

__device__ int g_fps[BB * MM];     // sentinel -1, written progressively by FPS
__device__ int g_nbr[BB * MM * SS];
__device__ int g_flag[BB * MM];    // per-query KNN done flag
__device__ int g_cnt[BB * 4];      // per-(b,chunk) KNN completion counter

// packed f32x2 helpers (lane-wise IEEE rn — bit-identical to scalar)
#define MUL_F32X2(out, a, b) \
    asm("mul.rn.f32x2 %0, %1, %2;" : "=l"(out) : "l"(a), "l"(b))
#define ADD_F32X2(out, a, b) \
    asm("add.rn.f32x2 %0, %1, %2;" : "=l"(out) : "l"(a), "l"(b))
#define PACK_F32X2(out, lo, hi) \
    asm("mov.b64 %0, {%1, %2};" : "=l"(out) : "f"(lo), "f"(hi))
#define UNPACK_F32X2(lo, hi, in) \
    asm("mov.b64 {%0, %1}, %2;" : "=f"(lo), "=f"(hi) : "l"(in))

__device__ __forceinline__ unsigned redux_max_u32(unsigned v) {
    unsigned r;
    asm volatile("redux.sync.max.u32 %0, %1, 0xffffffff;" : "=r"(r) : "r"(v));
    return r;
}

// strict (non-contracted) square-sum — matches reference fused square+reduce
__device__ __forceinline__ float sq3(float x, float y, float z) {
    return __fadd_rn(__fadd_rn(__fmul_rn(x, x), __fmul_rn(y, y)), __fmul_rn(z, z));
}

// ---------------------------------------------------------------------------
// init: sentinels/flags/counters (must run each graph replay)
// ---------------------------------------------------------------------------
__global__ void init_kernel() {
    int i = blockIdx.x * 256 + threadIdx.x;
    if (i < BB * MM) {
        g_fps[i] = -1;
        g_flag[i] = 0;
    }
    if (i < BB * 4) g_cnt[i] = 0;
}

// ---------------------------------------------------------------------------
// Mega-kernel (512 threads/block): block role by blockIdx.x
//   [0,2)           FPS (one per batch)               — wave-1 resident
//   [2,4098)        KNN (bid-2 = m*2+b)               — polls g_fps[m]
//   [4098,4354)     gxyz (256)                        — polls g_flag
//   [4354,5890)     gfts (1536: r + 384*chunk)        — polls g_cnt
// Dependencies flow strictly low-bid -> high-bid; FPS always resident.
// ---------------------------------------------------------------------------
#define NT 512
#define BID_KNN   2
#define BID_GXYZ  4098
#define BID_GFTS  4354
#define BID_TOTAL 5890

__global__ void __launch_bounds__(NT, 1)
mega_kernel(const float* __restrict__ xyz, const float* __restrict__ fts,
            float* __restrict__ out) {
    __shared__ float row[NN];          // gfts
    __shared__ float ctr[512];         // gfts
    __shared__ __align__(16) unsigned s_val[16];  // fps (16 warps)
    __shared__ int s_idx[2];           // fps
    __shared__ float s_v[16];          // knn
    __shared__ int   s_i[16];          // knn
    __shared__ int   s_b;              // knn

    const int bid = blockIdx.x;
    const int tid = threadIdx.x;

    // =====================================================================
    if (bid < BID_KNN) {
        // ---------------- FPS: 512 thr x 16 pts; packed strict distances
        const int b = bid;
        const float* p = xyz + (long)b * NN * 3;
        const int lane = tid & 31, warp = tid >> 5;
        volatile int* vfps = g_fps;

        // point i = j*512 + tid, j in [0,16); pairs (2k, 2k+1)
        unsigned long long px2[8], py2[8], pz2[8];
        float md[16];
#pragma unroll
        for (int k = 0; k < 8; k++) {
            int i0 = (2 * k) * NT + tid;
            int i1 = (2 * k + 1) * NT + tid;
            PACK_F32X2(px2[k], p[3 * i0 + 0], p[3 * i1 + 0]);
            PACK_F32X2(py2[k], p[3 * i0 + 1], p[3 * i1 + 1]);
            PACK_F32X2(pz2[k], p[3 * i0 + 2], p[3 * i1 + 2]);
            md[2 * k] = 1e10f;
            md[2 * k + 1] = 1e10f;
        }

        if (tid == 0) {
            vfps[b * MM] = 0;
            s_idx[0] = 0x7fffffff;
            s_idx[1] = 0x7fffffff;
        }
        __syncthreads();

        float lx = p[0], ly = p[1], lz = p[2];

        for (int it = 1; it < MM; it++) {
            unsigned long long nlx2, nly2, nlz2;
            float nlx = -lx, nly = -ly, nlz = -lz;
            PACK_F32X2(nlx2, nlx, nlx);
            PACK_F32X2(nly2, nly, nly);
            PACK_F32X2(nlz2, nlz, nlz);

            // 4 independent max accumulators (break the serial fmax chain)
            float a0 = -1.0f, a1 = -1.0f, a2 = -1.0f, a3 = -1.0f;
#pragma unroll
            for (int k = 0; k < 8; k++) {
                unsigned long long dx2, dy2, dz2, xx, yy, ss, zz, dd;
                ADD_F32X2(dx2, px2[k], nlx2);   // x - lx  (== x + (-lx))
                ADD_F32X2(dy2, py2[k], nly2);
                ADD_F32X2(dz2, pz2[k], nlz2);
                MUL_F32X2(xx, dx2, dx2);
                MUL_F32X2(yy, dy2, dy2);
                ADD_F32X2(ss, xx, yy);          // (dx² + dy²)
                MUL_F32X2(zz, dz2, dz2);
                ADD_F32X2(dd, ss, zz);          // + dz²
                float dlo, dhi;
                UNPACK_F32X2(dlo, dhi, dd);
                float m0 = fminf(md[2 * k], dlo);
                float m1 = fminf(md[2 * k + 1], dhi);
                md[2 * k] = m0;
                md[2 * k + 1] = m1;
                if (k & 1) { a2 = fmaxf(a2, m0); a3 = fmaxf(a3, m1); }
                else       { a0 = fmaxf(a0, m0); a1 = fmaxf(a1, m1); }
            }
            const float bv = fmaxf(fmaxf(a0, a1), fmaxf(a2, a3));

            // warp max (distances non-negative → u32 order == f32 order)
            const unsigned ub = __float_as_uint(bv);
            const unsigned wmax = redux_max_u32(ub);
            if (lane == 0) s_val[warp] = wmax;
            __syncthreads();                     // bar A

            // block max: 4x LDS.128 + 15 u32 max
            const uint4 v0 = *(const uint4*)&s_val[0];
            const uint4 v1 = *(const uint4*)&s_val[4];
            const uint4 v2 = *(const uint4*)&s_val[8];
            const uint4 v3 = *(const uint4*)&s_val[12];
            unsigned c0 = v0.x > v0.y ? v0.x : v0.y;
            unsigned c1 = v0.z > v0.w ? v0.z : v0.w;
            unsigned c2 = v1.x > v1.y ? v1.x : v1.y;
            unsigned c3 = v1.z > v1.w ? v1.z : v1.w;
            unsigned c4 = v2.x > v2.y ? v2.x : v2.y;
            unsigned c5 = v2.z > v2.w ? v2.z : v2.w;
            unsigned c6 = v3.x > v3.y ? v3.x : v3.y;
            unsigned c7 = v3.z > v3.w ? v3.z : v3.w;
            c0 = c0 > c1 ? c0 : c1;
            c2 = c2 > c3 ? c2 : c3;
            c4 = c4 > c5 ? c4 : c5;
            c6 = c6 > c7 ? c6 : c7;
            c0 = c0 > c2 ? c0 : c2;
            c4 = c4 > c6 ? c4 : c6;
            const unsigned bm = c0 > c4 ? c0 : c4;

            const int slot = it & 1;
            if (ub == bm) {
                // only block-max holders (typically 1 thread) pay the scan
                const float bmf = __uint_as_float(bm);
                unsigned mask = 0;
#pragma unroll
                for (int j = 0; j < 16; j++)
                    if (md[j] == bmf) mask |= (1u << j);
                int jmin = __ffs(mask) - 1;      // lowest j -> first index
                atomicMin(&s_idx[slot], jmin * NT + tid);
            }
            if (tid == 0) s_idx[slot ^ 1] = 0x7fffffff;
            __syncthreads();                     // bar B

            const int last = s_idx[slot];
            if (tid == 0) vfps[b * MM + it] = last;   // publish progressively
            lx = p[3 * last + 0];
            ly = p[3 * last + 1];
            lz = p[3 * last + 2];
        }
    }
    // =====================================================================
    else if (bid < BID_GXYZ) {
        // ------------- KNN (v10 exact), 512 thr x 16 dists, polls g_fps[m]
        const int bid2 = bid - BID_KNN;
        const int m = bid2 >> 1;
        const int b = bid2 & 1;
        const float* p = xyz + (long)b * NN * 3;
        const int t = tid;

        int qi;
        if (t == 0) {
            volatile int* vfps = g_fps;
            while ((qi = vfps[b * MM + m]) < 0) { }
            s_b = qi;
        }
        __syncthreads();
        qi = s_b;

        const float qx = p[3 * qi + 0], qy = p[3 * qi + 1], qz = p[3 * qi + 2];
        const float qq = sq3(qx, qy, qz);

        float d[16];
#pragma unroll
        for (int j = 0; j < 16; j++) {
            int i = j * NT + t;
            float x = p[3 * i + 0], y = p[3 * i + 1], z = p[3 * i + 2];
            float pp = sq3(x, y, z);
            float dot = __fmaf_rn(qz, z, __fmaf_rn(qy, y, __fmul_rn(qx, x)));
            d[j] = __fadd_rn(qq, __fsub_rn(pp, __fmul_rn(2.0f, dot)));
        }

        unsigned excl = 0u;
        float mv = d[0];
        int mi = t;
#pragma unroll
        for (int j = 1; j < 16; j++) {
            int i = j * NT + t;
            if (d[j] < mv) { mv = d[j]; mi = i; }  // strict < : lower idx on tie
        }

        const int lane = t & 31, w = t >> 5;
        const int out_base = (b * MM + m) * SS;

        for (int s = 0; s < SS; s++) {
            float bv = mv;
            int bi = mi;
#pragma unroll
            for (int o = 16; o > 0; o >>= 1) {
                float ov = __shfl_down_sync(0xffffffffu, bv, o);
                int   oi = __shfl_down_sync(0xffffffffu, bi, o);
                if (ov < bv || (ov == bv && oi < bi)) { bv = ov; bi = oi; }
            }
            if (lane == 0) { s_v[w] = bv; s_i[w] = bi; }
            __syncthreads();
            if (t == 0) {
                bv = s_v[0]; bi = s_i[0];
#pragma unroll
                for (int k = 1; k < 16; k++) {
                    float ov = s_v[k]; int oi = s_i[k];
                    if (ov < bv || (ov == bv && oi < bi)) { bv = ov; bi = oi; }
                }
                s_b = bi;
                g_nbr[out_base + s] = bi;
            }
            __syncthreads();
            int win = s_b;
            if ((win & (NT - 1)) == t) {
                excl |= 1u << (win >> 9);
                mv = 3.4e38f;
                mi = 0x7fffffff;
#pragma unroll
                for (int j = 0; j < 16; j++) {
                    if (!(excl & (1u << j))) {
                        int i = j * NT + t;
                        if (d[j] < mv) { mv = d[j]; mi = i; }
                    }
                }
            }
        }

        __syncthreads();
        if (t == 0) {
            __threadfence();                               // g_nbr visible
            ((volatile int*)g_flag)[b * MM + m] = 1;       // per-m flag
            atomicAdd(&g_cnt[b * 4 + (m >> 9)], 1);        // per-chunk counter
        }
    }
    // =====================================================================
    else if (bid < BID_GFTS) {
        // ------------------------------ gxyz + new_xyz, polls 16 flags
        const int bid3 = bid - BID_GXYZ;
        const int gtid = bid3 * NT + tid;   // over B*M*S = 131072
        const int s = gtid & 31;
        const int m = (gtid >> 5) & (MM - 1);
        const int b = gtid >> 16;

        // this block covers 16 consecutive m for one b
        if (tid < 16) {
            const int m0 = ((bid3 * NT) >> 5) & (MM - 1);
            const int bb = (bid3 * NT) >> 16;
            volatile int* vf = g_flag;
            while (vf[bb * MM + m0 + tid] == 0) { }
        }
        __syncthreads();

        const float* p = xyz + (long)b * NN * 3;
        int i = g_nbr[gtid];
        float* o = out + OFF_GXYZ + (long)gtid * 3;
        o[0] = p[3 * i + 0];
        o[1] = p[3 * i + 1];
        o[2] = p[3 * i + 2];

        if (s == 0) {
            int q = g_fps[b * MM + m];
            float* o2 = out + OFF_NXYZ + (long)(b * MM + m) * 3;
            o2[0] = p[3 * q + 0];
            o2[1] = p[3 * q + 1];
            o2[2] = p[3 * q + 2];
        }
    }
    // =====================================================================
    else {
        // ------------------------------ gfts + new_fts, polls chunk counter
        const int bid4 = bid - BID_GFTS;
        const int r = bid4 % 384;
        const int chunk = bid4 / 384;
        const int b = r / (CC * DD);
        const int cd = r % (CC * DD);
        const int c = cd / DD;
        const int dd = cd % DD;
        const int t = tid;

        if (t == 0) {
            volatile int* vc = g_cnt;
            while (vc[b * 4 + chunk] < 512) { }
        }
        __syncthreads();

        const float* src = fts + ((long)(b * CC + c) * DD + dd) * NN;
#pragma unroll
        for (int k = 0; k < 4; k++) {
            int i = (k * NT + t) * 4;
            *(float4*)&row[i] = *(const float4*)&src[i];
        }
        __syncthreads();

        const int m0 = chunk * 512;
        ctr[t] = row[g_fps[b * MM + m0 + t]];
        __syncthreads();

        float* o1 = out + OFF_GFTS + ((long)(b * 2 * CC + c) * DD + dd) * MM * SS;
        float* o2 = o1 + (long)CC * DD * MM * SS;
        const int* nb = g_nbr + (b * MM + m0) * SS;
        float* nfo1 = out + OFF_NFTS + ((long)(b * 2 * CC + c) * DD + dd) * MM + m0;
        float* nfo2 = nfo1 + (long)CC * DD * MM;

        for (int e = t; e < 512 * 8; e += NT) {
            int ml = e >> 3;
            int s4 = e & 7;
            int m = m0 + ml;
            int4 idx = *(const int4*)&nb[ml * SS + s4 * 4];
            float cv = ctr[ml];
            float4 v;
            v.x = __fsub_rn(row[idx.x], cv);
            v.y = __fsub_rn(row[idx.y], cv);
            v.z = __fsub_rn(row[idx.z], cv);
            v.w = __fsub_rn(row[idx.w], cv);
            long oo = (long)m * SS + s4 * 4;
            *(float4*)&o1[oo] = v;
            float4 cc4 = {cv, cv, cv, cv};
            *(float4*)&o2[oo] = cc4;
            if (s4 == 0) {
                nfo1[ml] = v.x;
                nfo2[ml] = cv;
            }
        }
    }
}

// ---------------------------------------------------------------------------
extern "C" void kernel_launch(void* const* d_in, const int* in_sizes, int n_in,
                              void* d_out, int out_size) {
    const float* xyz = (const float*)d_in[0];
    const float* fts = (const float*)d_in[1];
    if (n_in >= 2 && in_sizes[0] != BB * NN * 3) {
        const float* tmp = xyz; xyz = fts; fts = tmp;
    }
    float* out = (float*)d_out;

    init_kernel<<<(BB * MM + 255) / 256, 256>>>();
    mega_kernel<<<BID_TOTAL, NT>>>(xyz, fts, out);
}